// round 15
// baseline (speedup 1.0000x reference)
#include <cuda_runtime.h>
#include <cuda_bf16.h>
#include <cstdint>

// ---- problem dims ----
#define T_TOK 8192
#define H_DIM 5120
#define F_DIM 1536
#define N1 3072                 // gate|up output rows
#define N2 5120                 // H

// ---- GEMM tiling ----
#define BM 128
#define BN 256
#define BK 64
#define STAGES 4
#define STAGE_B ((BM + BN) * 128)             // 49152
#define SMEM_TOTAL (STAGES * STAGE_B)         // 196608

// ---- scratch: hi|lo packed, segments virtualized in the GEMM ----
static __device__ __align__(256) __nv_bfloat16 g_xcat [(size_t)T_TOK * 2 * H_DIM];
static __device__ __align__(256) __nv_bfloat16 g_w1cat[(size_t)N1   * 2 * H_DIM];
static __device__ __align__(256) __nv_bfloat16 g_wdcat[(size_t)N2   * 2 * F_DIM];
static __device__ __align__(256) float         g_c1   [(size_t)T_TOK * N1];
static __device__ __align__(256) __nv_bfloat16 g_hcat [(size_t)T_TOK * 2 * F_DIM];

// ---------------------------------------------------------------- helpers
__device__ __forceinline__ uint32_t smem_u32(const void* p) {
    uint32_t a;
    asm("{ .reg .u64 t; cvta.to.shared.u64 t, %1; cvt.u32.u64 %0, t; }"
        : "=r"(a) : "l"(p));
    return a;
}

#define LDMX4(r0, r1, r2, r3, addr) \
    asm volatile("ldmatrix.sync.aligned.m8n8.x4.shared.b16 {%0,%1,%2,%3}, [%4];" \
        : "=r"(r0), "=r"(r1), "=r"(r2), "=r"(r3) : "r"(addr))

#define MMA16816(c, a, b0, b1) \
    asm volatile("mma.sync.aligned.m16n8k16.row.col.f32.bf16.bf16.f32 " \
        "{%0,%1,%2,%3}, {%4,%5,%6,%7}, {%8,%9}, {%0,%1,%2,%3};" \
        : "+f"((c)[0]), "+f"((c)[1]), "+f"((c)[2]), "+f"((c)[3]) \
        : "r"((a)[0]), "r"((a)[1]), "r"((a)[2]), "r"((a)[3]), "r"(b0), "r"(b1))

__device__ __forceinline__ void st4bf(__nv_bfloat16* p, __nv_bfloat16 a, __nv_bfloat16 b,
                                      __nv_bfloat16 c, __nv_bfloat16 d) {
    union { __nv_bfloat16 h[4]; uint2 u; } t;
    t.h[0] = a; t.h[1] = b; t.h[2] = c; t.h[3] = d;
    *reinterpret_cast<uint2*>(p) = t.u;
}

__device__ __forceinline__ void split_bf(float v, __nv_bfloat16& hi, __nv_bfloat16& lo) {
    hi = __float2bfloat16(v);
    lo = __float2bfloat16(v - __bfloat162float(hi));
}

// ------------------------------------------------------------ prep kernels
// x[T,H] f32 -> g_xcat rows [xhi | xlo]   (width 2H)
__global__ void k_prep_x(const float* __restrict__ x) {
    size_t i = (size_t)blockIdx.x * blockDim.x + threadIdx.x;
    if (i >= (size_t)T_TOK * (H_DIM / 4)) return;
    int t  = (int)(i / (H_DIM / 4));
    int h  = 4 * (int)(i % (H_DIM / 4));
    float4 v = reinterpret_cast<const float4*>(x)[i];
    __nv_bfloat16 h0,h1,h2,h3,l0,l1,l2,l3;
    split_bf(v.x,h0,l0); split_bf(v.y,h1,l1); split_bf(v.z,h2,l2); split_bf(v.w,h3,l3);
    size_t rb = (size_t)t * (2*H_DIM) + h;
    st4bf(&g_xcat[rb],         h0,h1,h2,h3);
    st4bf(&g_xcat[rb + H_DIM], l0,l1,l2,l3);
}

// gate(0..F)|up(F..2F) dequantized -> g_w1cat rows [whi | wlo]
__global__ void k_prep_w1(const float* __restrict__ wg, const float* __restrict__ sg,
                          const float* __restrict__ wu, const float* __restrict__ su) {
    size_t i = (size_t)blockIdx.x * blockDim.x + threadIdx.x;
    if (i >= (size_t)N1 * (H_DIM / 4)) return;
    int f  = (int)(i / (H_DIM / 4));
    int h  = 4 * (int)(i % (H_DIM / 4));
    const float* w; float s;
    if (f < F_DIM) { w = wg + (size_t)f * H_DIM;
                     s = sg[(f >> 7) * (H_DIM/128) + (h >> 7)]; }
    else { int f2 = f - F_DIM; w = wu + (size_t)f2 * H_DIM;
           s = su[(f2 >> 7) * (H_DIM/128) + (h >> 7)]; }
    float4 v = *reinterpret_cast<const float4*>(w + h);
    v.x *= s; v.y *= s; v.z *= s; v.w *= s;
    __nv_bfloat16 h0,h1,h2,h3,l0,l1,l2,l3;
    split_bf(v.x,h0,l0); split_bf(v.y,h1,l1); split_bf(v.z,h2,l2); split_bf(v.w,h3,l3);
    size_t rb = (size_t)f * (2*H_DIM) + h;
    st4bf(&g_w1cat[rb],         h0,h1,h2,h3);
    st4bf(&g_w1cat[rb + H_DIM], l0,l1,l2,l3);
}

// w_down[H,F] dequantized -> g_wdcat rows [whi | wlo]
__global__ void k_prep_wd(const float* __restrict__ wd, const float* __restrict__ sd) {
    size_t i = (size_t)blockIdx.x * blockDim.x + threadIdx.x;
    if (i >= (size_t)N2 * (F_DIM / 4)) return;
    int o  = (int)(i / (F_DIM / 4));
    int fc = 4 * (int)(i % (F_DIM / 4));
    float s = sd[(o >> 7) * (F_DIM/128) + (fc >> 7)];
    float4 v = *reinterpret_cast<const float4*>(wd + (size_t)o * F_DIM + fc);
    v.x *= s; v.y *= s; v.z *= s; v.w *= s;
    __nv_bfloat16 h0,h1,h2,h3,l0,l1,l2,l3;
    split_bf(v.x,h0,l0); split_bf(v.y,h1,l1); split_bf(v.z,h2,l2); split_bf(v.w,h3,l3);
    size_t rb = (size_t)o * (2*F_DIM) + fc;
    st4bf(&g_wdcat[rb],         h0,h1,h2,h3);
    st4bf(&g_wdcat[rb + F_DIM], l0,l1,l2,l3);
}

// h = silu(gate)*up -> g_hcat rows [hhi | hlo]
__global__ void k_silu_h() {
    size_t i = (size_t)blockIdx.x * blockDim.x + threadIdx.x;
    if (i >= (size_t)T_TOK * (F_DIM / 4)) return;
    int t = (int)(i / (F_DIM / 4));
    int j = 4 * (int)(i % (F_DIM / 4));
    const float* row = g_c1 + (size_t)t * N1;
    float4 g = *reinterpret_cast<const float4*>(row + j);
    float4 u = *reinterpret_cast<const float4*>(row + F_DIM + j);
    float v0 = (g.x / (1.f + expf(-g.x))) * u.x;
    float v1 = (g.y / (1.f + expf(-g.y))) * u.y;
    float v2 = (g.z / (1.f + expf(-g.z))) * u.z;
    float v3 = (g.w / (1.f + expf(-g.w))) * u.w;
    __nv_bfloat16 h0,h1,h2,h3,l0,l1,l2,l3;
    split_bf(v0,h0,l0); split_bf(v1,h1,l1); split_bf(v2,h2,l2); split_bf(v3,h3,l3);
    size_t rb = (size_t)t * (2*F_DIM) + j;
    st4bf(&g_hcat[rb],         h0,h1,h2,h3);
    st4bf(&g_hcat[rb + F_DIM], l0,l1,l2,l3);
}

// ------------------------------------------------------- mma.sync GEMM
// Virtual 3-segment K: chunk cc in [0,3*cs) maps to physical byte offset
// within a row of the hi|lo packed operand. A segs {0,0,s2}, B segs {0,s1,0}.
__device__ __forceinline__ uint32_t choff(int cc, int cs, uint32_t o0, uint32_t o1, uint32_t o2) {
    int seg = (cc >= cs) + (cc >= 2 * cs);
    int ci  = cc - seg * cs;
    uint32_t base = (seg == 0) ? o0 : ((seg == 1) ? o1 : o2);
    return base + (uint32_t)ci * 128u;
}

struct FragA { uint32_t r[4][4]; };
struct FragB { uint32_t r[4][4]; };

__device__ __forceinline__ void load_frags(uint32_t sA, uint32_t sBm, uint32_t ks,
                                           const uint32_t* aBase, const uint32_t* aXor, uint32_t aG,
                                           const uint32_t* bBase, const uint32_t* bXor, uint32_t bG,
                                           FragA& a, FragB& b) {
#pragma unroll
    for (int mi = 0; mi < 4; mi++) {
        uint32_t ad = sA + aBase[mi] + ((((ks << 1) + aG) ^ aXor[mi]) << 4);
        LDMX4(a.r[mi][0], a.r[mi][1], a.r[mi][2], a.r[mi][3], ad);
    }
#pragma unroll
    for (int nj = 0; nj < 4; nj++) {
        uint32_t bd = sBm + bBase[nj] + ((((ks << 1) + bG) ^ bXor[nj]) << 4);
        LDMX4(b.r[nj][0], b.r[nj][1], b.r[nj][2], b.r[nj][3], bd);
    }
}

__device__ __forceinline__ void do_mma(float acc[4][8][4], const FragA& a, const FragB& b) {
#pragma unroll
    for (int mi = 0; mi < 4; mi++)
#pragma unroll
        for (int ni = 0; ni < 8; ni++)
            MMA16816(acc[mi][ni], a.r[mi],
                     b.r[ni >> 1][(ni & 1) * 2], b.r[ni >> 1][(ni & 1) * 2 + 1]);
}

__device__ __forceinline__ void issue_stage(uint32_t st, const char* Ab, const char* Bb,
                                            uint32_t ao, uint32_t bo,
                                            const uint32_t* swOffA, const uint32_t* gOffA,
                                            const uint32_t* swOffB, const uint32_t* gOffB) {
#pragma unroll
    for (int j = 0; j < 4; j++)
        asm volatile("cp.async.cg.shared.global [%0], [%1], 16;"
                     :: "r"(st + swOffA[j]), "l"(Ab + ao + gOffA[j]));
#pragma unroll
    for (int j = 0; j < 8; j++)
        asm volatile("cp.async.cg.shared.global [%0], [%1], 16;"
                     :: "r"(st + (BM * 128) + swOffB[j]), "l"(Bb + bo + gOffB[j]));
    asm volatile("cp.async.commit_group;" ::: "memory");
}

// C[8192,N] f32 = A(vcat)[8192,3*cs*64]·B(vcat)[N,3*cs*64]^T; ld = physical row bytes.
__global__ void __launch_bounds__(256, 1)
k_gemm(const char* __restrict__ A, const char* __restrict__ B, float* __restrict__ C,
       int ld, int cs, int N, uint32_t aS2, uint32_t bS1)
{
    extern __shared__ char smem[];
    const int tid = threadIdx.x, lane = tid & 31, wid = tid >> 5;
    const int wm = (wid >> 2) << 6;   // 0 / 64
    const int wn = (wid & 3) << 6;    // 0/64/128/192
    const uint32_t sb = smem_u32(smem);

    // CTA swizzle (GROUP_M=8)
    const int numN = N / BN;
    const int gsize = 8 * numN;
    const int grp = blockIdx.x / gsize, rem = blockIdx.x % gsize;
    const int m0 = (grp * 8 + (rem & 7)) * BM;
    const int n0 = (rem >> 3) * BN;

    const char* gA = A + (size_t)m0 * ld;
    const char* gB = B + (size_t)n0 * ld;

    uint32_t swOffA[4], gOffA[4], swOffB[8], gOffB[8];
#pragma unroll
    for (int j = 0; j < 4; j++) {
        int idx = tid + 256 * j, r = idx >> 3, g = idx & 7;
        swOffA[j] = (uint32_t)(r * 128 + ((g ^ (r & 7)) << 4));
        gOffA[j]  = (uint32_t)(r * ld + g * 16);
    }
#pragma unroll
    for (int j = 0; j < 8; j++) {
        int idx = tid + 256 * j, r = idx >> 3, g = idx & 7;
        swOffB[j] = (uint32_t)(r * 128 + ((g ^ (r & 7)) << 4));
        gOffB[j]  = (uint32_t)(r * ld + g * 16);
    }

    uint32_t aBase[4], aXor[4];
#pragma unroll
    for (int mi = 0; mi < 4; mi++) {
        int r = wm + mi * 16 + (lane & 15);
        aBase[mi] = (uint32_t)(r * 128);
        aXor[mi]  = (uint32_t)(r & 7);
    }
    uint32_t bBase[4], bXor[4];
#pragma unroll
    for (int nj = 0; nj < 4; nj++) {
        int r = wn + nj * 16 + ((lane >> 4) << 3) + (lane & 7);
        bBase[nj] = (uint32_t)(r * 128);
        bXor[nj]  = (uint32_t)(r & 7);
    }
    const uint32_t aG = (uint32_t)(lane >> 4);
    const uint32_t bG = (uint32_t)((lane >> 3) & 1);

    float acc[4][8][4];
#pragma unroll
    for (int mi = 0; mi < 4; mi++)
#pragma unroll
        for (int ni = 0; ni < 8; ni++)
#pragma unroll
            for (int q = 0; q < 4; q++) acc[mi][ni][q] = 0.f;

    const int nc = 3 * cs;

    // prologue: stages 0..2
#pragma unroll
    for (int c = 0; c < STAGES - 1; c++)
        issue_stage(sb + c * STAGE_B, gA, gB,
                    choff(c, cs, 0u, 0u, aS2), choff(c, cs, 0u, bS1, 0u),
                    swOffA, gOffA, swOffB, gOffB);
    asm volatile("cp.async.wait_group %0;" :: "n"(STAGES - 2) : "memory");
    __syncthreads();

    FragA a[2]; FragB b[2];
    load_frags(sb, sb + BM * 128, 0, aBase, aXor, aG, bBase, bXor, bG, a[0], b[0]);

    int stage = 0;
    for (int cc = 0; cc < nc; cc++) {
        uint32_t sA = sb + stage * STAGE_B, sBm = sA + BM * 128;
#pragma unroll
        for (int ks = 0; ks < 4; ks++) {
            if (ks < 3) {
                load_frags(sA, sBm, (uint32_t)(ks + 1), aBase, aXor, aG,
                           bBase, bXor, bG, a[(ks + 1) & 1], b[(ks + 1) & 1]);
            } else if (cc + 1 < nc) {
                // chunk boundary: prefetch, drain, sync, load next-chunk ks0
                if (cc + STAGES - 1 < nc) {
                    int c2 = cc + STAGES - 1;
                    issue_stage(sb + ((stage + STAGES - 1) & 3) * STAGE_B, gA, gB,
                                choff(c2, cs, 0u, 0u, aS2), choff(c2, cs, 0u, bS1, 0u),
                                swOffA, gOffA, swOffB, gOffB);
                    asm volatile("cp.async.wait_group %0;" :: "n"(STAGES - 2) : "memory");
                } else if (cc + STAGES - 2 < nc) {
                    asm volatile("cp.async.wait_group %0;" :: "n"(STAGES - 3) : "memory");
                } else {
                    asm volatile("cp.async.wait_group 0;" ::: "memory");
                }
                __syncthreads();
                uint32_t nsA = sb + ((stage + 1) & 3) * STAGE_B;
                load_frags(nsA, nsA + BM * 128, 0, aBase, aXor, aG,
                           bBase, bXor, bG, a[0], b[0]);
            }
            do_mma(acc, a[ks & 1], b[ks & 1]);
        }
        stage = (stage + 1) & 3;
    }

    // epilogue
    const int rbase = m0 + wm + (lane >> 2);
    const int cbase = n0 + wn + (lane & 3) * 2;
#pragma unroll
    for (int mi = 0; mi < 4; mi++) {
#pragma unroll
        for (int ni = 0; ni < 8; ni++) {
            size_t r0 = (size_t)(rbase + mi * 16) * N + (cbase + ni * 8);
            *reinterpret_cast<float2*>(C + r0) =
                make_float2(acc[mi][ni][0], acc[mi][ni][1]);
            *reinterpret_cast<float2*>(C + r0 + 8 * (size_t)N) =
                make_float2(acc[mi][ni][2], acc[mi][ni][3]);
        }
    }
}

// ------------------------------------------------------------ launch
extern "C" void kernel_launch(void* const* d_in, const int* in_sizes, int n_in,
                              void* d_out, int out_size) {
    (void)in_sizes; (void)n_in; (void)out_size;
    const float* x  = (const float*)d_in[0];
    const float* wg = (const float*)d_in[1];
    const float* sg = (const float*)d_in[2];
    const float* wu = (const float*)d_in[3];
    const float* su = (const float*)d_in[4];
    const float* wd = (const float*)d_in[5];
    const float* sd = (const float*)d_in[6];
    float* out = (float*)d_out;

    cudaFuncSetAttribute(k_gemm, cudaFuncAttributeMaxDynamicSharedMemorySize, SMEM_TOTAL);

    void *pxc, *pw1, *pwd, *pc1, *phc;
    cudaGetSymbolAddress(&pxc, g_xcat);
    cudaGetSymbolAddress(&pw1, g_w1cat);
    cudaGetSymbolAddress(&pwd, g_wdcat);
    cudaGetSymbolAddress(&pc1, g_c1);
    cudaGetSymbolAddress(&phc, g_hcat);

    k_prep_x <<<(T_TOK * (H_DIM/4) + 255) / 256, 256>>>(x);
    k_prep_w1<<<(N1    * (H_DIM/4) + 255) / 256, 256>>>(wg, sg, wu, su);
    k_prep_wd<<<(N2    * (F_DIM/4) + 255) / 256, 256>>>(wd, sd);

    // GEMM1: ld = 4*H bytes/row ; cs = H/64 ; A segs {0,0,2H}, B segs {0,2H,0} (bytes)
    k_gemm<<<(T_TOK / BM) * (N1 / BN), 256, SMEM_TOTAL>>>(
        (const char*)pxc, (const char*)pw1, (float*)pc1,
        4 * H_DIM, H_DIM / 64, N1, (uint32_t)(2 * H_DIM), (uint32_t)(2 * H_DIM));

    k_silu_h<<<(T_TOK * (F_DIM/4) + 255) / 256, 256>>>();

    // GEMM2: ld = 4*F ; cs = F/64
    k_gemm<<<(T_TOK / BM) * (N2 / BN), 256, SMEM_TOTAL>>>(
        (const char*)phc, (const char*)pwd, out,
        4 * F_DIM, F_DIM / 64, N2, (uint32_t)(2 * F_DIM), (uint32_t)(2 * F_DIM));
}

// round 16
// speedup vs baseline: 1.1588x; 1.1588x over previous
#include <cuda_runtime.h>
#include <cuda_bf16.h>
#include <cstdint>

// ---- problem dims ----
#define T_TOK 8192
#define H_DIM 5120
#define F_DIM 1536
#define N1 3072                 // gate|up output rows
#define N2 5120                 // H

// ---- GEMM tiling: 128x128 CTA, 4 warps (64x64 each), 2 CTAs/SM ----
#define BM 128
#define BN 128
#define BK 64
#define STAGES 3
#define STAGE_B ((BM + BN) * 128)             // 32768
#define SMEM_TOTAL (STAGES * STAGE_B)         // 98304 per CTA

// ---- scratch: hi|lo packed, segments virtualized in the GEMM ----
static __device__ __align__(256) __nv_bfloat16 g_xcat [(size_t)T_TOK * 2 * H_DIM];
static __device__ __align__(256) __nv_bfloat16 g_w1cat[(size_t)N1   * 2 * H_DIM];
static __device__ __align__(256) __nv_bfloat16 g_wdcat[(size_t)N2   * 2 * F_DIM];
static __device__ __align__(256) float         g_c1   [(size_t)T_TOK * N1];
static __device__ __align__(256) __nv_bfloat16 g_hcat [(size_t)T_TOK * 2 * F_DIM];

// ---------------------------------------------------------------- helpers
__device__ __forceinline__ uint32_t smem_u32(const void* p) {
    uint32_t a;
    asm("{ .reg .u64 t; cvta.to.shared.u64 t, %1; cvt.u32.u64 %0, t; }"
        : "=r"(a) : "l"(p));
    return a;
}

#define LDMX4(r0, r1, r2, r3, addr) \
    asm volatile("ldmatrix.sync.aligned.m8n8.x4.shared.b16 {%0,%1,%2,%3}, [%4];" \
        : "=r"(r0), "=r"(r1), "=r"(r2), "=r"(r3) : "r"(addr))

#define MMA16816(c, a, b0, b1) \
    asm volatile("mma.sync.aligned.m16n8k16.row.col.f32.bf16.bf16.f32 " \
        "{%0,%1,%2,%3}, {%4,%5,%6,%7}, {%8,%9}, {%0,%1,%2,%3};" \
        : "+f"((c)[0]), "+f"((c)[1]), "+f"((c)[2]), "+f"((c)[3]) \
        : "r"((a)[0]), "r"((a)[1]), "r"((a)[2]), "r"((a)[3]), "r"(b0), "r"(b1))

__device__ __forceinline__ void st4bf(__nv_bfloat16* p, __nv_bfloat16 a, __nv_bfloat16 b,
                                      __nv_bfloat16 c, __nv_bfloat16 d) {
    union { __nv_bfloat16 h[4]; uint2 u; } t;
    t.h[0] = a; t.h[1] = b; t.h[2] = c; t.h[3] = d;
    *reinterpret_cast<uint2*>(p) = t.u;
}

__device__ __forceinline__ void split_bf(float v, __nv_bfloat16& hi, __nv_bfloat16& lo) {
    hi = __float2bfloat16(v);
    lo = __float2bfloat16(v - __bfloat162float(hi));
}

// ------------------------------------------------------------ prep kernels
// x[T,H] f32 -> g_xcat rows [xhi | xlo]   (width 2H)
__global__ void k_prep_x(const float* __restrict__ x) {
    size_t i = (size_t)blockIdx.x * blockDim.x + threadIdx.x;
    if (i >= (size_t)T_TOK * (H_DIM / 4)) return;
    int t  = (int)(i / (H_DIM / 4));
    int h  = 4 * (int)(i % (H_DIM / 4));
    float4 v = reinterpret_cast<const float4*>(x)[i];
    __nv_bfloat16 h0,h1,h2,h3,l0,l1,l2,l3;
    split_bf(v.x,h0,l0); split_bf(v.y,h1,l1); split_bf(v.z,h2,l2); split_bf(v.w,h3,l3);
    size_t rb = (size_t)t * (2*H_DIM) + h;
    st4bf(&g_xcat[rb],         h0,h1,h2,h3);
    st4bf(&g_xcat[rb + H_DIM], l0,l1,l2,l3);
}

// gate(0..F)|up(F..2F) dequantized -> g_w1cat rows [whi | wlo]
__global__ void k_prep_w1(const float* __restrict__ wg, const float* __restrict__ sg,
                          const float* __restrict__ wu, const float* __restrict__ su) {
    size_t i = (size_t)blockIdx.x * blockDim.x + threadIdx.x;
    if (i >= (size_t)N1 * (H_DIM / 4)) return;
    int f  = (int)(i / (H_DIM / 4));
    int h  = 4 * (int)(i % (H_DIM / 4));
    const float* w; float s;
    if (f < F_DIM) { w = wg + (size_t)f * H_DIM;
                     s = sg[(f >> 7) * (H_DIM/128) + (h >> 7)]; }
    else { int f2 = f - F_DIM; w = wu + (size_t)f2 * H_DIM;
           s = su[(f2 >> 7) * (H_DIM/128) + (h >> 7)]; }
    float4 v = *reinterpret_cast<const float4*>(w + h);
    v.x *= s; v.y *= s; v.z *= s; v.w *= s;
    __nv_bfloat16 h0,h1,h2,h3,l0,l1,l2,l3;
    split_bf(v.x,h0,l0); split_bf(v.y,h1,l1); split_bf(v.z,h2,l2); split_bf(v.w,h3,l3);
    size_t rb = (size_t)f * (2*H_DIM) + h;
    st4bf(&g_w1cat[rb],         h0,h1,h2,h3);
    st4bf(&g_w1cat[rb + H_DIM], l0,l1,l2,l3);
}

// w_down[H,F] dequantized -> g_wdcat rows [whi | wlo]
__global__ void k_prep_wd(const float* __restrict__ wd, const float* __restrict__ sd) {
    size_t i = (size_t)blockIdx.x * blockDim.x + threadIdx.x;
    if (i >= (size_t)N2 * (F_DIM / 4)) return;
    int o  = (int)(i / (F_DIM / 4));
    int fc = 4 * (int)(i % (F_DIM / 4));
    float s = sd[(o >> 7) * (F_DIM/128) + (fc >> 7)];
    float4 v = *reinterpret_cast<const float4*>(wd + (size_t)o * F_DIM + fc);
    v.x *= s; v.y *= s; v.z *= s; v.w *= s;
    __nv_bfloat16 h0,h1,h2,h3,l0,l1,l2,l3;
    split_bf(v.x,h0,l0); split_bf(v.y,h1,l1); split_bf(v.z,h2,l2); split_bf(v.w,h3,l3);
    size_t rb = (size_t)o * (2*F_DIM) + fc;
    st4bf(&g_wdcat[rb],         h0,h1,h2,h3);
    st4bf(&g_wdcat[rb + F_DIM], l0,l1,l2,l3);
}

// h = silu(gate)*up -> g_hcat rows [hhi | hlo]
__global__ void k_silu_h() {
    size_t i = (size_t)blockIdx.x * blockDim.x + threadIdx.x;
    if (i >= (size_t)T_TOK * (F_DIM / 4)) return;
    int t = (int)(i / (F_DIM / 4));
    int j = 4 * (int)(i % (F_DIM / 4));
    const float* row = g_c1 + (size_t)t * N1;
    float4 g = *reinterpret_cast<const float4*>(row + j);
    float4 u = *reinterpret_cast<const float4*>(row + F_DIM + j);
    float v0 = (g.x / (1.f + expf(-g.x))) * u.x;
    float v1 = (g.y / (1.f + expf(-g.y))) * u.y;
    float v2 = (g.z / (1.f + expf(-g.z))) * u.z;
    float v3 = (g.w / (1.f + expf(-g.w))) * u.w;
    __nv_bfloat16 h0,h1,h2,h3,l0,l1,l2,l3;
    split_bf(v0,h0,l0); split_bf(v1,h1,l1); split_bf(v2,h2,l2); split_bf(v3,h3,l3);
    size_t rb = (size_t)t * (2*F_DIM) + j;
    st4bf(&g_hcat[rb],         h0,h1,h2,h3);
    st4bf(&g_hcat[rb + F_DIM], l0,l1,l2,l3);
}

// ------------------------------------------------------- mma.sync GEMM
// Virtual 3-segment K: chunk cc in [0,3*cs) maps to physical byte offset
// within a row of the hi|lo packed operand. A segs {0,0,s2}, B segs {0,s1,0}.
__device__ __forceinline__ uint32_t choff(int cc, int cs, uint32_t o0, uint32_t o1, uint32_t o2) {
    int seg = (cc >= cs) + (cc >= 2 * cs);
    int ci  = cc - seg * cs;
    uint32_t base = (seg == 0) ? o0 : ((seg == 1) ? o1 : o2);
    return base + (uint32_t)ci * 128u;
}

struct FragA { uint32_t r[4][4]; };
struct FragB { uint32_t r[4][4]; };

__device__ __forceinline__ void load_frags(uint32_t sA, uint32_t sBm, uint32_t ks,
                                           const uint32_t* aBase, const uint32_t* aXor, uint32_t aG,
                                           const uint32_t* bBase, const uint32_t* bXor, uint32_t bG,
                                           FragA& a, FragB& b) {
#pragma unroll
    for (int mi = 0; mi < 4; mi++) {
        uint32_t ad = sA + aBase[mi] + ((((ks << 1) + aG) ^ aXor[mi]) << 4);
        LDMX4(a.r[mi][0], a.r[mi][1], a.r[mi][2], a.r[mi][3], ad);
    }
#pragma unroll
    for (int nj = 0; nj < 4; nj++) {
        uint32_t bd = sBm + bBase[nj] + ((((ks << 1) + bG) ^ bXor[nj]) << 4);
        LDMX4(b.r[nj][0], b.r[nj][1], b.r[nj][2], b.r[nj][3], bd);
    }
}

__device__ __forceinline__ void do_mma(float acc[4][8][4], const FragA& a, const FragB& b) {
#pragma unroll
    for (int mi = 0; mi < 4; mi++)
#pragma unroll
        for (int ni = 0; ni < 8; ni++)
            MMA16816(acc[mi][ni], a.r[mi],
                     b.r[ni >> 1][(ni & 1) * 2], b.r[ni >> 1][(ni & 1) * 2 + 1]);
}

__device__ __forceinline__ void issue_stage(uint32_t st, const char* Ab, const char* Bb,
                                            uint32_t ao, uint32_t bo,
                                            const uint32_t* swOff, const uint32_t* gOff) {
#pragma unroll
    for (int j = 0; j < 8; j++)
        asm volatile("cp.async.cg.shared.global [%0], [%1], 16;"
                     :: "r"(st + swOff[j]), "l"(Ab + ao + gOff[j]));
#pragma unroll
    for (int j = 0; j < 8; j++)
        asm volatile("cp.async.cg.shared.global [%0], [%1], 16;"
                     :: "r"(st + (BM * 128) + swOff[j]), "l"(Bb + bo + gOff[j]));
    asm volatile("cp.async.commit_group;" ::: "memory");
}

// C[8192,N] f32 = A(vcat)[8192,3*cs*64]·B(vcat)[N,3*cs*64]^T; ld = physical row bytes.
// 128 threads, 4 warps (2x2), warp tile 64x64, 2 CTAs/SM.
__global__ void __launch_bounds__(128, 2)
k_gemm(const char* __restrict__ A, const char* __restrict__ B, float* __restrict__ C,
       int ld, int cs, int N, uint32_t aS2, uint32_t bS1)
{
    extern __shared__ char smem[];
    const int tid = threadIdx.x, lane = tid & 31, wid = tid >> 5;
    const int wm = (wid >> 1) << 6;   // 0 / 64
    const int wn = (wid & 1) << 6;    // 0 / 64
    const uint32_t sb = smem_u32(smem);

    // CTA swizzle (GROUP_M=8)
    const int numN = N / BN;
    const int gsize = 8 * numN;
    const int grp = blockIdx.x / gsize, rem = blockIdx.x % gsize;
    const int m0 = (grp * 8 + (rem & 7)) * BM;
    const int n0 = (rem >> 3) * BN;

    const char* gA = A + (size_t)m0 * ld;
    const char* gB = B + (size_t)n0 * ld;

    // cp.async mapping: 128 threads, 8 chunks each for A and B
    uint32_t swOff[8], gOff[8];
#pragma unroll
    for (int j = 0; j < 8; j++) {
        int idx = tid + 128 * j, r = idx >> 3, g = idx & 7;
        swOff[j] = (uint32_t)(r * 128 + ((g ^ (r & 7)) << 4));
        gOff[j]  = (uint32_t)(r * ld + g * 16);
    }

    uint32_t aBase[4], aXor[4];
#pragma unroll
    for (int mi = 0; mi < 4; mi++) {
        int r = wm + mi * 16 + (lane & 15);
        aBase[mi] = (uint32_t)(r * 128);
        aXor[mi]  = (uint32_t)(r & 7);
    }
    uint32_t bBase[4], bXor[4];
#pragma unroll
    for (int nj = 0; nj < 4; nj++) {
        int r = wn + nj * 16 + ((lane >> 4) << 3) + (lane & 7);
        bBase[nj] = (uint32_t)(r * 128);
        bXor[nj]  = (uint32_t)(r & 7);
    }
    const uint32_t aG = (uint32_t)(lane >> 4);
    const uint32_t bG = (uint32_t)((lane >> 3) & 1);

    float acc[4][8][4];
#pragma unroll
    for (int mi = 0; mi < 4; mi++)
#pragma unroll
        for (int ni = 0; ni < 8; ni++)
#pragma unroll
            for (int q = 0; q < 4; q++) acc[mi][ni][q] = 0.f;

    const int nc = 3 * cs;

    // prologue: stages 0,1
#pragma unroll
    for (int c = 0; c < STAGES - 1; c++)
        issue_stage(sb + c * STAGE_B, gA, gB,
                    choff(c, cs, 0u, 0u, aS2), choff(c, cs, 0u, bS1, 0u), swOff, gOff);
    asm volatile("cp.async.wait_group %0;" :: "n"(STAGES - 2) : "memory");
    __syncthreads();

    FragA a[2]; FragB b[2];
    load_frags(sb, sb + BM * 128, 0, aBase, aXor, aG, bBase, bXor, bG, a[0], b[0]);

    int stage = 0;
    for (int cc = 0; cc < nc; cc++) {
        uint32_t sA = sb + stage * STAGE_B, sBm = sA + BM * 128;
#pragma unroll
        for (int ks = 0; ks < 4; ks++) {
            if (ks < 3) {
                load_frags(sA, sBm, (uint32_t)(ks + 1), aBase, aXor, aG,
                           bBase, bXor, bG, a[(ks + 1) & 1], b[(ks + 1) & 1]);
            } else if (cc + 1 < nc) {
                // chunk boundary: prefetch (dist 2), drain, sync, load next ks0
                if (cc + 2 < nc) {
                    int c2 = cc + 2;
                    int nst = stage - 1; if (nst < 0) nst += STAGES;
                    issue_stage(sb + nst * STAGE_B, gA, gB,
                                choff(c2, cs, 0u, 0u, aS2), choff(c2, cs, 0u, bS1, 0u),
                                swOff, gOff);
                    asm volatile("cp.async.wait_group 1;" ::: "memory");
                } else {
                    asm volatile("cp.async.wait_group 0;" ::: "memory");
                }
                __syncthreads();
                int nxt = stage + 1; if (nxt == STAGES) nxt = 0;
                uint32_t nsA = sb + nxt * STAGE_B;
                load_frags(nsA, nsA + BM * 128, 0, aBase, aXor, aG,
                           bBase, bXor, bG, a[0], b[0]);
            }
            do_mma(acc, a[ks & 1], b[ks & 1]);
        }
        stage = stage + 1; if (stage == STAGES) stage = 0;
    }

    // epilogue
    const int rbase = m0 + wm + (lane >> 2);
    const int cbase = n0 + wn + (lane & 3) * 2;
#pragma unroll
    for (int mi = 0; mi < 4; mi++) {
#pragma unroll
        for (int ni = 0; ni < 8; ni++) {
            size_t r0 = (size_t)(rbase + mi * 16) * N + (cbase + ni * 8);
            *reinterpret_cast<float2*>(C + r0) =
                make_float2(acc[mi][ni][0], acc[mi][ni][1]);
            *reinterpret_cast<float2*>(C + r0 + 8 * (size_t)N) =
                make_float2(acc[mi][ni][2], acc[mi][ni][3]);
        }
    }
}

// ------------------------------------------------------------ launch
extern "C" void kernel_launch(void* const* d_in, const int* in_sizes, int n_in,
                              void* d_out, int out_size) {
    (void)in_sizes; (void)n_in; (void)out_size;
    const float* x  = (const float*)d_in[0];
    const float* wg = (const float*)d_in[1];
    const float* sg = (const float*)d_in[2];
    const float* wu = (const float*)d_in[3];
    const float* su = (const float*)d_in[4];
    const float* wd = (const float*)d_in[5];
    const float* sd = (const float*)d_in[6];
    float* out = (float*)d_out;

    cudaFuncSetAttribute(k_gemm, cudaFuncAttributeMaxDynamicSharedMemorySize, SMEM_TOTAL);

    void *pxc, *pw1, *pwd, *pc1, *phc;
    cudaGetSymbolAddress(&pxc, g_xcat);
    cudaGetSymbolAddress(&pw1, g_w1cat);
    cudaGetSymbolAddress(&pwd, g_wdcat);
    cudaGetSymbolAddress(&pc1, g_c1);
    cudaGetSymbolAddress(&phc, g_hcat);

    k_prep_x <<<(T_TOK * (H_DIM/4) + 255) / 256, 256>>>(x);
    k_prep_w1<<<(N1    * (H_DIM/4) + 255) / 256, 256>>>(wg, sg, wu, su);
    k_prep_wd<<<(N2    * (F_DIM/4) + 255) / 256, 256>>>(wd, sd);

    // GEMM1: ld = 4*H bytes/row ; cs = H/64 ; A segs {0,0,2H}, B segs {0,2H,0} (bytes)
    k_gemm<<<(T_TOK / BM) * (N1 / BN), 128, SMEM_TOTAL>>>(
        (const char*)pxc, (const char*)pw1, (float*)pc1,
        4 * H_DIM, H_DIM / 64, N1, (uint32_t)(2 * H_DIM), (uint32_t)(2 * H_DIM));

    k_silu_h<<<(T_TOK * (F_DIM/4) + 255) / 256, 256>>>();

    // GEMM2: ld = 4*F ; cs = F/64
    k_gemm<<<(T_TOK / BM) * (N2 / BN), 128, SMEM_TOTAL>>>(
        (const char*)phc, (const char*)pwd, out,
        4 * F_DIM, F_DIM / 64, N2, (uint32_t)(2 * F_DIM), (uint32_t)(2 * F_DIM));
}